// round 16
// baseline (speedup 1.0000x reference)
#include <cuda_runtime.h>
#include <math.h>
#include <stddef.h>

// Problem constants
#define BATCH 4
#define HH 48
#define WW 48
#define DD 64
#define HC 46                 // valid patch grid
#define CC 2116               // HC*HC candidate patches
#define MM 2304               // HH*WW locations
#define TEMPR 50.0f

// Scratch (device globals -- no runtime allocation allowed)
static __device__ float g_E [(size_t)BATCH * MM * MM];   // E Gram, then Sc (85 MB)
static __device__ float g_DS[(size_t)BATCH * MM * CC];   // CA (78 MB)
static __device__ float g_bg [BATCH * MM * DD];          // g_in * mask
static __device__ float g_bgc[BATCH * MM * DD];          // compacted bg rows
static __device__ float g_sg [BATCH * MM];               // per-pixel sum g^2
static __device__ float g_sbg[BATCH * MM];               // per-pixel sum bg^2
static __device__ float g_wwd[BATCH * MM];               // 3x3 box sum (same pad) of g_sg
static __device__ float g_k1d[BATCH * CC];               // 3x3 box sum (valid) of g_sbg
static __device__ float g_ACL[BATCH * MM * DD];
static __device__ int   g_qlist[BATCH * MM];             // ascending nonzero-mask pixels
static __device__ int   g_Kc [BATCH];                    // count
static __device__ int   g_Kcp[BATCH];                    // count padded to 16

// ---------------------------------------------------------------------------
// Kernel 0a: bg = g_in * mask ; per-pixel sums of squares
__global__ void prep_kernel(const float* __restrict__ gin, const float* __restrict__ mask) {
    int p = blockIdx.x;
    int d = threadIdx.x;
    float mv = mask[p];
    float g  = gin[p * DD + d];
    float bgv = g * mv;
    g_bg[p * DD + d] = bgv;
    __shared__ float s1[DD];
    __shared__ float s2[DD];
    s1[d] = g * g;
    s2[d] = bgv * bgv;
    __syncthreads();
    #pragma unroll
    for (int s = 32; s > 0; s >>= 1) {
        if (d < s) { s1[d] += s1[d + s]; s2[d] += s2[d + s]; }
        __syncthreads();
    }
    if (d == 0) { g_sg[p] = s1[0]; g_sbg[p] = s2[0]; }
}

// Kernel 0b: box sums -> wwd (same pad) and k1d (valid)
__global__ void boxsum_kernel() {
    int idx = blockIdx.x * blockDim.x + threadIdx.x;
    if (idx < BATCH * MM) {
        int b = idx / MM, m = idx - b * MM;
        int y = m / WW, x = m - y * WW;
        float s = 0.f;
        #pragma unroll
        for (int dy = 0; dy < 3; dy++)
            #pragma unroll
            for (int dx = 0; dx < 3; dx++) {
                int yy = y + dy - 1, xx = x + dx - 1;
                if (yy >= 0 && yy < HH && xx >= 0 && xx < WW)
                    s += g_sg[(b * HH + yy) * WW + xx];
            }
        g_wwd[idx] = s;
    } else if (idx < BATCH * MM + BATCH * CC) {
        int id2 = idx - BATCH * MM;
        int b = id2 / CC, j = id2 - b * CC;
        int jy = j / HC, jx = j - jy * HC;
        float s = 0.f;
        #pragma unroll
        for (int dy = 0; dy < 3; dy++)
            #pragma unroll
            for (int dx = 0; dx < 3; dx++)
                s += g_sbg[(b * HH + jy + dy) * WW + jx + dx];
        g_k1d[id2] = s;
    }
}

// ---------------------------------------------------------------------------
// scan: deterministic block scan (no atomics) -> qlist of nonzero-mask pixels
__global__ __launch_bounds__(256) void scan_kernel(const float* __restrict__ mask) {
    int b = blockIdx.x;
    int tid = threadIdx.x;
    int lane = tid & 31, wid = tid >> 5;
    __shared__ int wsum[8];
    __shared__ int sbase;
    if (tid == 0) sbase = 0;
    __syncthreads();
    for (int c0 = 0; c0 < MM; c0 += 256) {
        int q = c0 + tid;
        int f = (mask[b * MM + q] != 0.f) ? 1 : 0;
        int incl = f;
        #pragma unroll
        for (int o = 1; o < 32; o <<= 1) {
            int t = __shfl_up_sync(0xffffffffu, incl, o);
            if (lane >= o) incl += t;
        }
        if (lane == 31) wsum[wid] = incl;
        __syncthreads();
        int woff = 0;
        #pragma unroll
        for (int w = 0; w < 8; w++) if (w < wid) woff += wsum[w];
        int excl = sbase + woff + incl - f;
        if (f) g_qlist[b * MM + excl] = q;
        __syncthreads();
        if (tid == 0) {
            int tot = 0;
            #pragma unroll
            for (int w = 0; w < 8; w++) tot += wsum[w];
            sbase += tot;
        }
        __syncthreads();
    }
    if (tid == 0) {
        g_Kc[b]  = sbase;
        g_Kcp[b] = (sbase + 15) & ~15;
    }
}

// compact bg rows (float4, 256 threads, 64 k-rows per block)
__global__ __launch_bounds__(256) void compact_bg_kernel() {
    int b = blockIdx.y;
    int base = blockIdx.x * 64;
    int Kc = g_Kc[b], Kcp = g_Kcp[b];
    if (base >= Kcp) return;
    int tid = threadIdx.x;
    #pragma unroll
    for (int r = 0; r < 4; r++) {
        int idx = tid + 256 * r;          // 0..1023 -> 64 rows x 16 float4
        int k = base + (idx >> 4);
        int c = (idx & 15) * 4;
        if (k < Kcp) {
            float4 v = make_float4(0.f, 0.f, 0.f, 0.f);
            if (k < Kc) {
                int q = g_qlist[b * MM + k];
                v = *(const float4*)&g_bg[((size_t)b * MM + q) * DD + c];
            }
            *(float4*)&g_bgc[((size_t)b * MM + k) * DD + c] = v;
        }
    }
}

// ---------------------------------------------------------------------------
// gemmE (SYRK, 64 threads, 8x8 microtile -> LDS:FMA balanced 1:1).
// G = gin @ gin^T symmetric; E[p,q] = G[p,q]*mask[q].  Lower tiles only;
// mirror tile staged through smem overlay for coalesced writes.
#define NTILE (MM / 64)                       // 36
#define NPAIR (NTILE * (NTILE + 1) / 2)       // 666
__global__ __launch_bounds__(64) void gemmE_syrk_kernel(const float* __restrict__ gin,
                                                        const float* __restrict__ mask) {
    __shared__ float As[64][68];   // [k][row], padded
    __shared__ float Bs[64][68];

    int b = blockIdx.y;
    int t = blockIdx.x;
    int i = (int)((sqrtf(8.f * t + 1.f) - 1.f) * 0.5f);
    while ((i + 1) * (i + 2) / 2 <= t) i++;
    while (i * (i + 1) / 2 > t) i--;
    int j = t - i * (i + 1) / 2;
    int p0 = i * 64;
    int q0 = j * 64;

    int tid = threadIdx.x;
    int ty = tid >> 3, tx = tid & 7;   // 8x8 thread grid

    const float* A = gin + (size_t)b * MM * DD;

    // load 64 rows x 64 k for both tiles
    #pragma unroll
    for (int rp = 0; rp < 4; rp++) {
        int row = (tid >> 2) + rp * 16;
        #pragma unroll
        for (int kp = 0; kp < 4; kp++) {
            int k0 = kp * 16 + (tid & 3) * 4;
            float4 va = *(const float4*)(A + (p0 + row) * DD + k0);
            As[k0 + 0][row] = va.x; As[k0 + 1][row] = va.y;
            As[k0 + 2][row] = va.z; As[k0 + 3][row] = va.w;
            float4 vb = *(const float4*)(A + (q0 + row) * DD + k0);
            Bs[k0 + 0][row] = vb.x; Bs[k0 + 1][row] = vb.y;
            Bs[k0 + 2][row] = vb.z; Bs[k0 + 3][row] = vb.w;
        }
    }
    __syncthreads();

    float acc[8][8];
    #pragma unroll
    for (int r = 0; r < 8; r++)
        #pragma unroll
        for (int c = 0; c < 8; c++) acc[r][c] = 0.f;

    #pragma unroll 4
    for (int k = 0; k < DD; k++) {
        float4 a0 = *(const float4*)(&As[k][ty * 8]);
        float4 a1 = *(const float4*)(&As[k][ty * 8 + 4]);
        float4 b0 = *(const float4*)(&Bs[k][tx * 8]);
        float4 b1 = *(const float4*)(&Bs[k][tx * 8 + 4]);
        float av[8] = {a0.x, a0.y, a0.z, a0.w, a1.x, a1.y, a1.z, a1.w};
        float bv[8] = {b0.x, b0.y, b0.z, b0.w, b1.x, b1.y, b1.z, b1.w};
        #pragma unroll
        for (int r = 0; r < 8; r++)
            #pragma unroll
            for (int c = 0; c < 8; c++) acc[r][c] += av[r] * bv[c];
    }

    float* Eb = g_E + (size_t)b * MM * MM;
    const float* mb = mask + b * MM;

    // normal write: E[p0+row, q0+col] = acc * mask[col]   (coalesced float4)
    float mq[8];
    #pragma unroll
    for (int c = 0; c < 8; c++) mq[c] = mb[q0 + tx * 8 + c];
    #pragma unroll
    for (int r = 0; r < 8; r++) {
        float* rp = Eb + (size_t)(p0 + ty * 8 + r) * MM + q0 + tx * 8;
        float4 v0, v1;
        v0.x = acc[r][0] * mq[0]; v0.y = acc[r][1] * mq[1];
        v0.z = acc[r][2] * mq[2]; v0.w = acc[r][3] * mq[3];
        v1.x = acc[r][4] * mq[4]; v1.y = acc[r][5] * mq[5];
        v1.z = acc[r][6] * mq[6]; v1.w = acc[r][7] * mq[7];
        *(float4*)(rp + 0) = v0;
        *(float4*)(rp + 4) = v1;
    }

    if (i != j) {
        float mp[8];
        #pragma unroll
        for (int r = 0; r < 8; r++) mp[r] = mb[p0 + ty * 8 + r];
        __syncthreads();                       // done reading As/Bs
        float (*sT)[68] = As;                  // overlay transpose staging
        #pragma unroll
        for (int r = 0; r < 8; r++)
            #pragma unroll
            for (int c = 0; c < 8; c++)
                sT[tx * 8 + c][ty * 8 + r] = acc[r][c] * mp[r];
        __syncthreads();
        #pragma unroll
        for (int it = 0; it < 16; it++) {
            int idx = tid + 64 * it;           // 0..1023
            int row = idx >> 4;
            int ch  = idx & 15;
            float4 v = *(const float4*)(&sT[row][ch * 4]);
            *(float4*)(Eb + (size_t)(q0 + row) * MM + p0 + ch * 4) = v;
        }
    }
}

// ---------------------------------------------------------------------------
__device__ __forceinline__ float block_sum256(float v, float* red) {
    int tid = threadIdx.x;
    #pragma unroll
    for (int o = 16; o > 0; o >>= 1) v += __shfl_xor_sync(0xffffffffu, v, o);
    __syncthreads();
    if ((tid & 31) == 0) red[tid >> 5] = v;
    __syncthreads();
    float tot = red[0] + red[1] + red[2] + red[3] + red[4] + red[5] + red[6] + red[7];
    return tot;
}

// ---------------------------------------------------------------------------
// Fused DS + tanh-normalized softmax.  One CTA per output row m.
__global__ __launch_bounds__(256) void ds_softmax_kernel() {
    __shared__ float red[8];
    int row = blockIdx.x;
    int b = row / MM, m = row - b * MM;
    int y = m / WW, x = m - y * WW;
    int tid = threadIdx.x;

    const float* Eb = g_E + (size_t)b * MM * MM;
    const float* base = Eb + (ptrdiff_t)((y - 1) * WW + (x - 1)) * MM;
    float wv = g_wwd[row];
    const float* k1 = g_k1d + b * CC;

    bool tvy[3], tvx[3];
    #pragma unroll
    for (int t = 0; t < 3; t++) {
        tvy[t] = (unsigned)(y + t - 1) < (unsigned)HH;
        tvx[t] = (unsigned)(x + t - 1) < (unsigned)WW;
    }
    bool interior = tvy[0] && tvy[2] && tvx[0] && tvx[2];

    float v[9];
    float s = 0.f;

    if (interior) {
        #pragma unroll
        for (int i = 0; i < 9; i++) {
            int n = tid + 256 * i;
            if (n < CC) {
                int jy = n / HC, jx = n - jy * HC;
                const float* p = base + (jy * WW + jx);
                float cs = 0.f;
                #pragma unroll
                for (int dy = 0; dy < 3; dy++)
                    #pragma unroll
                    for (int dx = 0; dx < 3; dx++)
                        cs += p[(dy * WW + dx) * (MM + 1)];
                float val = fmaf(-2.f, cs, k1[n] + wv);
                v[i] = val;
                s += val;
            } else v[i] = 0.f;
        }
    } else {
        #pragma unroll
        for (int i = 0; i < 9; i++) {
            int n = tid + 256 * i;
            if (n < CC) {
                int jy = n / HC, jx = n - jy * HC;
                const float* p = base + (jy * WW + jx);
                float cs = 0.f;
                #pragma unroll
                for (int dy = 0; dy < 3; dy++)
                    #pragma unroll
                    for (int dx = 0; dx < 3; dx++)
                        if (tvy[dy] && tvx[dx])
                            cs += p[(dy * WW + dx) * (MM + 1)];
                float val = fmaf(-2.f, cs, k1[n] + wv);
                v[i] = val;
                s += val;
            } else v[i] = 0.f;
        }
    }

    float mu = block_sum256(s, red) * (1.0f / CC);

    float s2 = 0.f;
    #pragma unroll
    for (int i = 0; i < 9; i++) {
        int n = tid + 256 * i;
        if (n < CC) { float d = v[i] - mu; s2 = fmaf(d, d, s2); }
    }
    float isd = rsqrtf(block_sum256(s2, red) * (1.0f / CC));

    float se = 0.f;
    #pragma unroll
    for (int i = 0; i < 9; i++) {
        int n = tid + 256 * i;
        if (n < CC) {
            float w = (v[i] - mu) * isd;
            float u = __expf(2.f * w);
            float e = __expf(__fdividef(100.f, u + 1.f) - 50.f);
            v[i] = e;
            se += e;
        }
    }
    float inv = 1.0f / block_sum256(se, red);

    float* rp = g_DS + (size_t)row * CC;
    #pragma unroll
    for (int i = 0; i < 9; i++) {
        int n = tid + 256 * i;
        if (n < CC) rp[n] = v[i] * inv;
    }
}

// ---------------------------------------------------------------------------
// S gather (COMPACTED): Sc[m,k] for k in [0,Kcp), q = qlist[k] ascending.
// Paired rows (y, y+1) per CTA for CA line reuse.  Pad cols -> 0.
__global__ __launch_bounds__(256) void s_gather_kernel() {
    int pid = blockIdx.x;
    int b = pid / (MM / 2);
    int mp = pid - b * (MM / 2);
    int yh = mp / WW, x = mp - yh * WW;
    int y0 = yh * 2;
    int tid = threadIdx.x;
    int Kc = g_Kc[b], Kcp = g_Kcp[b];

    const float* CAb = g_DS + (size_t)b * MM * CC;
    const float* base0 = CAb + (ptrdiff_t)((y0 + 1) * WW + (x + 1)) * CC;
    const float* base1 = base0 + (ptrdiff_t)WW * CC;
    const int* ql = g_qlist + b * MM;

    unsigned pm0 = 0, pm1 = 0;
    #pragma unroll
    for (int dy = 0; dy < 3; dy++)
        #pragma unroll
        for (int dx = 0; dx < 3; dx++) {
            bool xv = (unsigned)(x + 1 - dx) < (unsigned)WW;
            if (xv && (unsigned)(y0 + 1 - dy) < (unsigned)HH) pm0 |= 1u << (dy * 3 + dx);
            if (xv && (unsigned)(y0 + 2 - dy) < (unsigned)HH) pm1 |= 1u << (dy * 3 + dx);
        }
    bool full0 = (pm0 == 0x1FFu), full1 = (pm1 == 0x1FFu);

    float* Sout0 = g_E + (size_t)b * MM * MM + (size_t)(y0 * WW + x) * MM;
    float* Sout1 = Sout0 + (size_t)WW * MM;

    for (int k = tid; k < Kcp; k += 256) {
        float s0 = 0.f, s1 = 0.f;
        if (k < Kc) {
            int q = ql[k];
            int qy = q / WW, qx = q - qy * WW;
            int cb = qy * HC + qx;
            const float* p0 = base0 + cb;
            const float* p1 = base1 + cb;
            if (full0 && full1 && qy >= 2 && qy <= 45 && qx >= 2 && qx <= 45) {
                #pragma unroll
                for (int dy = 0; dy < 3; dy++)
                    #pragma unroll
                    for (int dx = 0; dx < 3; dx++) {
                        int off = -(dy * (WW * CC + HC) + dx * (CC + 1));
                        s0 += p0[off];
                        s1 += p1[off];
                    }
            } else {
                unsigned pq = 0;
                #pragma unroll
                for (int dy = 0; dy < 3; dy++)
                    #pragma unroll
                    for (int dx = 0; dx < 3; dx++)
                        if ((unsigned)(qy - dy) < (unsigned)HC &&
                            (unsigned)(qx - dx) < (unsigned)HC)
                            pq |= 1u << (dy * 3 + dx);
                unsigned e0 = pm0 & pq, e1 = pm1 & pq;
                #pragma unroll
                for (int dy = 0; dy < 3; dy++)
                    #pragma unroll
                    for (int dx = 0; dx < 3; dx++) {
                        int bit = dy * 3 + dx;
                        int off = -(dy * (WW * CC + HC) + dx * (CC + 1));
                        if (e0 & (1u << bit)) s0 += p0[off];
                        if (e1 & (1u << bit)) s1 += p1[off];
                    }
            }
        }
        Sout0[k] = s0;
        Sout1[k] = s1;
    }
}

// ---------------------------------------------------------------------------
// gemm_acl (compacted K, 64 threads, 8x4 microtile): acl[m,d] = sum Sc*bgc.
// BM=64, BN=32, BK=16, double-buffered + register prefetch.
__global__ __launch_bounds__(64) void gemm_acl_kernel(const float* __restrict__ mask) {
    __shared__ float As[2][16][68];
    __shared__ float Bs[2][16][32];
    int b  = blockIdx.z;
    int m0 = blockIdx.x * 64;
    int n0 = blockIdx.y * 32;
    int tid = threadIdx.x;
    int ty = tid >> 3, tx = tid & 7;    // 8x8 thread grid, micro 8x4
    int nkt = g_Kcp[b] >> 4;

    int arb = tid >> 2;                 // base A row (0..15), +16*r
    int akc = (tid & 3) * 4;            // A k-chunk
    int bkb = tid >> 3;                 // base B k (0..7), +8*r
    int bcc = (tid & 7) * 4;            // B col chunk

    const float* Sb  = g_E   + (size_t)b * MM * MM + (size_t)m0 * MM;
    const float* bgc = g_bgc + (size_t)b * MM * DD;

    float acc[8][4];
    #pragma unroll
    for (int r = 0; r < 8; r++)
        #pragma unroll
        for (int c = 0; c < 4; c++) acc[r][c] = 0.f;

    if (nkt > 0) {
        float4 pa[4], pb[2];
        #pragma unroll
        for (int r = 0; r < 4; r++)
            pa[r] = *(const float4*)(Sb + (size_t)(arb + 16 * r) * MM + akc);
        #pragma unroll
        for (int r = 0; r < 2; r++)
            pb[r] = *(const float4*)(bgc + (bkb + 8 * r) * DD + n0 + bcc);
        #pragma unroll
        for (int r = 0; r < 4; r++) {
            int ar = arb + 16 * r;
            As[0][akc + 0][ar] = pa[r].x; As[0][akc + 1][ar] = pa[r].y;
            As[0][akc + 2][ar] = pa[r].z; As[0][akc + 3][ar] = pa[r].w;
        }
        #pragma unroll
        for (int r = 0; r < 2; r++)
            *(float4*)(&Bs[0][bkb + 8 * r][bcc]) = pb[r];
        __syncthreads();

        for (int t = 0; t < nkt; t++) {
            int cur = t & 1;
            if (t + 1 < nkt) {
                int k0 = (t + 1) * 16;
                #pragma unroll
                for (int r = 0; r < 4; r++)
                    pa[r] = *(const float4*)(Sb + (size_t)(arb + 16 * r) * MM + k0 + akc);
                #pragma unroll
                for (int r = 0; r < 2; r++)
                    pb[r] = *(const float4*)(bgc + (k0 + bkb + 8 * r) * DD + n0 + bcc);
            }
            #pragma unroll
            for (int k = 0; k < 16; k++) {
                float4 a0 = *(const float4*)(&As[cur][k][ty * 8]);
                float4 a1 = *(const float4*)(&As[cur][k][ty * 8 + 4]);
                float4 b4 = *(const float4*)(&Bs[cur][k][tx * 4]);
                float av[8] = {a0.x, a0.y, a0.z, a0.w, a1.x, a1.y, a1.z, a1.w};
                float bv[4] = {b4.x, b4.y, b4.z, b4.w};
                #pragma unroll
                for (int r = 0; r < 8; r++)
                    #pragma unroll
                    for (int c = 0; c < 4; c++) acc[r][c] += av[r] * bv[c];
            }
            if (t + 1 < nkt) {
                int nxt = 1 - cur;
                #pragma unroll
                for (int r = 0; r < 4; r++) {
                    int ar = arb + 16 * r;
                    As[nxt][akc + 0][ar] = pa[r].x; As[nxt][akc + 1][ar] = pa[r].y;
                    As[nxt][akc + 2][ar] = pa[r].z; As[nxt][akc + 3][ar] = pa[r].w;
                }
                #pragma unroll
                for (int r = 0; r < 2; r++)
                    *(float4*)(&Bs[nxt][bkb + 8 * r][bcc]) = pb[r];
            }
            __syncthreads();
        }
    }

    #pragma unroll
    for (int r = 0; r < 8; r++) {
        int rowm = b * MM + m0 + ty * 8 + r;
        float om = (1.f - mask[rowm]) * (1.f / 9.f);
        int idx = rowm * DD + n0 + tx * 4;
        float4 v;
        v.x = g_bg[idx + 0] + acc[r][0] * om;
        v.y = g_bg[idx + 1] + acc[r][1] * om;
        v.z = g_bg[idx + 2] + acc[r][2] * om;
        v.w = g_bg[idx + 3] + acc[r][3] * om;
        *(float4*)(&g_ACL[idx]) = v;
    }
}

// ---------------------------------------------------------------------------
// Final: out = elu(concat(g_in, ACL) @ W2 + b2).  4 rows x 64 cols per block.
__global__ __launch_bounds__(256) void final_kernel(const float* __restrict__ gin,
                                                    const float* __restrict__ W2,
                                                    const float* __restrict__ b2,
                                                    float* __restrict__ out) {
    __shared__ float sA[4][128];
    int r0 = blockIdx.x * 4;
    int tid = threadIdx.x;
    for (int idx = tid; idx < 512; idx += 256) {
        int r = idx >> 7, k = idx & 127;
        int row = r0 + r;
        sA[r][k] = (k < DD) ? gin[row * DD + k] : g_ACL[row * DD + (k - DD)];
    }
    __syncthreads();
    int r = tid >> 6, d = tid & 63;
    int row = r0 + r;
    float acc = b2[d];
    #pragma unroll 8
    for (int k = 0; k < 128; k++) acc += sA[r][k] * W2[k * DD + d];
    out[row * DD + d] = (acc > 0.f) ? acc : expm1f(acc);
}

// ---------------------------------------------------------------------------
extern "C" void kernel_launch(void* const* d_in, const int* in_sizes, int n_in,
                              void* d_out, int out_size) {
    const float* gin  = (const float*)d_in[0];
    const float* mask = (const float*)d_in[1];
    const float* W2   = (const float*)d_in[2];
    const float* b2   = (const float*)d_in[3];
    float* out = (float*)d_out;

    prep_kernel<<<BATCH * MM, DD>>>(gin, mask);
    int tot = BATCH * MM + BATCH * CC;
    boxsum_kernel<<<(tot + 255) / 256, 256>>>();
    scan_kernel<<<BATCH, 256>>>(mask);
    compact_bg_kernel<<<dim3(MM / 64, BATCH), 256>>>();
    gemmE_syrk_kernel<<<dim3(NPAIR, BATCH), 64>>>(gin, mask);
    ds_softmax_kernel<<<BATCH * MM, 256>>>();
    s_gather_kernel<<<BATCH * MM / 2, 256>>>();
    gemm_acl_kernel<<<dim3(MM / 64, DD / 32, BATCH), 64>>>(mask);
    final_kernel<<<BATCH * MM / 4, 256>>>(gin, W2, b2, out);
}